// round 3
// baseline (speedup 1.0000x reference)
#include <cuda_runtime.h>
#include <math.h>

#define NQ 4
#define SDIM 16
#define KCOLS 512

__global__ __launch_bounds__(128) void qnet_kernel(
    const float* __restrict__ A,       // [B,512]
    const float* __restrict__ pre_w,   // [4,512]
    const float* __restrict__ pre_b,   // [4]
    const float* __restrict__ u3p,     // [4,3]
    const float* __restrict__ post_w,  // [2,4]
    const float* __restrict__ post_b,  // [2]
    float* __restrict__ out,           // [B,2]
    int B)
{
    __shared__ float4 w4[KCOLS];       // w4[c] = (w0[c], w1[c], w2[c], w3[c])
    __shared__ float  g[NQ][8];        // u3 gate: {g00, g01r,g01i, g10r,g10i, g11r,g11i, pad}

    const int tid = threadIdx.x;

    // Load pre_w transposed into smem
    for (int c = tid; c < KCOLS; c += blockDim.x) {
        w4[c] = make_float4(pre_w[c],
                            pre_w[KCOLS + c],
                            pre_w[2 * KCOLS + c],
                            pre_w[3 * KCOLS + c]);
    }
    // Compute the 4 batch-independent U3 gate matrices once per block
    if (tid < NQ) {
        const int q = tid;
        float th = u3p[q * 3 + 0], ph = u3p[q * 3 + 1], la = u3p[q * 3 + 2];
        float ct, st, cl, sl, cp, sp;
        sincosf(0.5f * th, &st, &ct);
        sincosf(la, &sl, &cl);
        sincosf(ph, &sp, &cp);
        float cpl = cp * cl - sp * sl;  // cos(phi+lam)
        float spl = sp * cl + cp * sl;  // sin(phi+lam)
        g[q][0] = ct;
        g[q][1] = -cl * st;  g[q][2] = -sl * st;   // g01 = -e^{i lam} sin
        g[q][3] =  cp * st;  g[q][4] =  sp * st;   // g10 =  e^{i phi} sin
        g[q][5] =  cpl * ct; g[q][6] =  spl * ct;  // g11 =  e^{i(phi+lam)} cos
        g[q][7] = 0.0f;
    }
    __syncthreads();

    const int b = blockIdx.x * blockDim.x + tid;
    if (b >= B) return;

    // ---------------- GEMM: 4 dot products of length 512 ----------------
    const float4* row = (const float4*)(A + (size_t)b * KCOLS);
    float a0 = 0.f, a1 = 0.f, a2 = 0.f, a3 = 0.f;
    #pragma unroll 8
    for (int i = 0; i < KCOLS / 4; i++) {
        float4 x  = row[i];
        float4 wa = w4[4 * i + 0];
        float4 wb = w4[4 * i + 1];
        float4 wc = w4[4 * i + 2];
        float4 wd = w4[4 * i + 3];
        a0 += x.x * wa.x + x.y * wb.x + x.z * wc.x + x.w * wd.x;
        a1 += x.x * wa.y + x.y * wb.y + x.z * wc.y + x.w * wd.y;
        a2 += x.x * wa.z + x.y * wb.z + x.z * wc.z + x.w * wd.z;
        a3 += x.x * wa.w + x.y * wb.w + x.z * wc.w + x.w * wd.w;
    }

    // ---------------- Angle preprocessing ----------------
    float pre[NQ];
    pre[0] = a0 + pre_b[0];
    pre[1] = a1 + pre_b[1];
    pre[2] = a2 + pre_b[2];
    pre[3] = a3 + pre_b[3];

    float ryc[NQ], rys[NQ], rzc[NQ], rzs[NQ];
    #pragma unroll
    for (int q = 0; q < NQ; q++) {
        float t  = tanhf(pre[q] * 0.1f) * 1.5707963267948966f;  // q_in
        float ry = atanf(t);
        float rz = atanf(t * t);
        __sincosf(0.5f * ry, &rys[q], &ryc[q]);   // |arg| < 0.5
        __sincosf(0.5f * rz, &rzs[q], &rzc[q]);   // |arg| < 0.6
    }

    // ---------------- Statevector simulation (registers) ----------------
    float re[SDIM], im[SDIM];
    // H^{x4} |0...0> = 0.25 everywhere (real)
    #pragma unroll
    for (int i = 0; i < SDIM; i++) { re[i] = 0.25f; im[i] = 0.0f; }

    // RY layer (real rotation: state stays real)
    #pragma unroll
    for (int q = 0; q < NQ; q++) {
        const int bit = 8 >> q;
        const float c = ryc[q], s = rys[q];
        #pragma unroll
        for (int i = 0; i < SDIM; i++) {
            if (!(i & bit)) {
                float r0 = re[i], r1 = re[i | bit];
                re[i]       = c * r0 - s * r1;
                re[i | bit] = s * r0 + c * r1;
            }
        }
    }

    // RZ layer: multiply amplitude i by (c, +/- s) depending on bit q
    #pragma unroll
    for (int q = 0; q < NQ; q++) {
        const int bit = 8 >> q;
        const float c = rzc[q], sz = rzs[q];
        #pragma unroll
        for (int i = 0; i < SDIM; i++) {
            float s = (i & bit) ? sz : -sz;
            float r = re[i], m = im[i];
            re[i] = r * c - m * s;
            im[i] = r * s + m * c;
        }
    }

    // CNOT rings: pure register permutations
    #define CNOT_(cq, tq)                                                  \
    {                                                                      \
        const int bc = 8 >> (cq), bt = 8 >> (tq);                          \
        _Pragma("unroll")                                                  \
        for (int i = 0; i < SDIM; i++) {                                   \
            if ((i & bc) && !(i & bt)) {                                   \
                float tr = re[i]; re[i] = re[i | bt]; re[i | bt] = tr;     \
                float tm = im[i]; im[i] = im[i | bt]; im[i | bt] = tm;     \
            }                                                              \
        }                                                                  \
    }
    CNOT_(0, 1); CNOT_(1, 2); CNOT_(2, 3); CNOT_(3, 0);   // step 1 ring
    CNOT_(0, 2); CNOT_(1, 3); CNOT_(2, 0); CNOT_(3, 1);   // step 2 ring
    #undef CNOT_

    // U3 layer (full complex 2x2 per qubit; gates from smem broadcast)
    #pragma unroll
    for (int q = 0; q < NQ; q++) {
        const int bit = 8 >> q;
        const float g00  = g[q][0];
        const float g01r = g[q][1], g01i = g[q][2];
        const float g10r = g[q][3], g10i = g[q][4];
        const float g11r = g[q][5], g11i = g[q][6];
        #pragma unroll
        for (int i = 0; i < SDIM; i++) {
            if (!(i & bit)) {
                const int j = i | bit;
                float r0 = re[i], m0 = im[i], r1 = re[j], m1 = im[j];
                re[i] = g00 * r0 + g01r * r1 - g01i * m1;
                im[i] = g00 * m0 + g01r * m1 + g01i * r1;
                re[j] = g10r * r0 - g10i * m0 + g11r * r1 - g11i * m1;
                im[j] = g10r * m0 + g10i * r0 + g11r * m1 + g11i * r1;
            }
        }
    }

    // Z expectations per qubit
    float e0 = 0.f, e1 = 0.f, e2 = 0.f, e3 = 0.f;
    #pragma unroll
    for (int i = 0; i < SDIM; i++) {
        float p = re[i] * re[i] + im[i] * im[i];
        e0 += (i & 8) ? -p : p;
        e1 += (i & 4) ? -p : p;
        e2 += (i & 2) ? -p : p;
        e3 += (i & 1) ? -p : p;
    }

    // Post projection [2,4]
    float o0 = post_b[0] + e0 * post_w[0] + e1 * post_w[1] + e2 * post_w[2] + e3 * post_w[3];
    float o1 = post_b[1] + e0 * post_w[4] + e1 * post_w[5] + e2 * post_w[6] + e3 * post_w[7];
    ((float2*)out)[b] = make_float2(o0, o1);
}

extern "C" void kernel_launch(void* const* d_in, const int* in_sizes, int n_in,
                              void* d_out, int out_size) {
    const float* A      = (const float*)d_in[0];   // input_features [B,512]
    const float* pre_w  = (const float*)d_in[1];   // [4,512]
    const float* pre_b  = (const float*)d_in[2];   // [4]
    const float* u3p    = (const float*)d_in[3];   // [4,3]
    const float* post_w = (const float*)d_in[4];   // [2,4]
    const float* post_b = (const float*)d_in[5];   // [2]
    float* out          = (float*)d_out;           // [B,2]

    const int B = in_sizes[0] / KCOLS;
    const int block = 128;
    const int grid  = (B + block - 1) / block;
    qnet_kernel<<<grid, block>>>(A, pre_w, pre_b, u3p, post_w, post_b, out, B);
}